// round 2
// baseline (speedup 1.0000x reference)
#include <cuda_runtime.h>
#include <cstddef>

// Problem constants (fixed by the reference setup)
#define SV     4        // S
#define DV     2048     // DIM
#define NVN    2048     // N
#define BVB    4        // B
#define KTOT   8192     // S*DIM (reduction length)
#define NCOL   24       // 20 alpha cols + 4 beta cols
#define PTOT   8192     // B*N
#define KB_N   8        // K-split blocks (each 1024)

// ----------------------------------------------------------------------------
// Scratch (static device globals; no runtime allocation allowed)
// ----------------------------------------------------------------------------
__device__ float g_Acomb[KTOT * NCOL];          // (1+gamma)-folded [alpha_fn | beta_fn]
__device__ float g_part[KB_N * 25 * PTOT];      // partial dots: [kb][c][p], c=24 is sumsq
__device__ float g_W[PTOT * 16];                // final 4x4 mixing matrix per (b,n)

// ----------------------------------------------------------------------------
// f32x2 packed-FMA helpers (Blackwell sm_100a+)
// ----------------------------------------------------------------------------
__device__ __forceinline__ void fma2(unsigned long long &d,
                                     unsigned long long a,
                                     unsigned long long b) {
    asm("fma.rn.f32x2 %0, %1, %2, %0;" : "+l"(d) : "l"(a), "l"(b));
}
__device__ __forceinline__ float2 unpk2(unsigned long long v) {
    float2 f;
    asm("mov.b64 {%0, %1}, %2;" : "=f"(f.x), "=f"(f.y) : "l"(v));
    return f;
}

// ----------------------------------------------------------------------------
// Kernel 0: build Acomb = (1+gamma) * [dynamic_alpha_fn | dynamic_beta_fn]
// ----------------------------------------------------------------------------
__global__ void prep_kernel(const float* __restrict__ afn,
                            const float* __restrict__ bfn,
                            const float* __restrict__ gamma) {
    int idx = blockIdx.x * 256 + threadIdx.x;
    if (idx >= KTOT * NCOL) return;
    int i = idx / NCOL;
    int c = idx - i * NCOL;
    float g = 1.0f + gamma[i];
    float v = (c < 20) ? afn[i * 20 + c] : bfn[i * 4 + (c - 20)];
    g_Acomb[idx] = v * g;
}

// ----------------------------------------------------------------------------
// Kernel 1: tall-skinny GEMM + sumsq.
// Grid: (64 p-tiles of 128 n each, 8 K-blocks of 1024). 256 threads.
// Per CTA: smem-tiled (KC=32), thread tile 4p x 3c via f32x2 FMA.
// ----------------------------------------------------------------------------
__global__ __launch_bounds__(256) void dots_kernel(const float* __restrict__ res) {
    const int tid = threadIdx.x;
    const int pt  = blockIdx.x;          // 0..63
    const int kb  = blockIdx.y;          // 0..7
    const int p0  = pt * 128;
    const int b   = p0 >> 11;            // p = b*2048 + n
    const int n0  = p0 & 2047;
    const int s   = kb >> 1;
    const int j0  = (kb & 1) << 10;

    __shared__ float  sRs[32 * 128];     // [k][n]  16 KB
    __shared__ float2 sAs[32 * 24];      // [k][c] duplicated pairs, 6 KB

    // ---- loader mapping: thread -> (n within tile, half of 32-k chunk)
    const int ln = tid >> 1;             // 0..127
    const int lh = tid & 1;              // 0/1
    const float* gsrc = res
        + ((size_t)((b * 4 + s) * 2048 + (n0 + ln))) * 2048 + j0 + lh * 16;
    const float* asrc = g_Acomb + (size_t)(s * 2048 + j0) * NCOL;

    // ---- compute mapping: 8 warps = 4 p-groups x 2 c-groups
    const int warp = tid >> 5, lane = tid & 31;
    const int pg = warp & 3, cg = warp >> 2;
    const int tp = lane & 7, tc = lane >> 3;
    const int prow  = pg * 32 + tp * 4;      // 4 consecutive p
    const int cbase = cg * 12 + tc * 3;      // 3 consecutive c

    unsigned long long acc[3][2];
    #pragma unroll
    for (int i = 0; i < 3; i++)
        #pragma unroll
        for (int j = 0; j < 2; j++) acc[i][j] = 0ull;
    float ssq = 0.0f;

    for (int ch = 0; ch < 32; ch++) {
        // global loads into registers (before barrier, overlap with prev compute)
        float4 v[4];
        #pragma unroll
        for (int w = 0; w < 4; w++)
            v[w] = *(const float4*)(gsrc + ch * 32 + w * 4);
        float a[3];
        #pragma unroll
        for (int q = 0; q < 3; q++)
            a[q] = asrc[ch * 32 * NCOL + tid + q * 256];

        __syncthreads();   // previous chunk's compute done

        #pragma unroll
        for (int w = 0; w < 4; w++) {
            int k = lh * 16 + w * 4;
            sRs[(k + 0) * 128 + ln] = v[w].x;
            sRs[(k + 1) * 128 + ln] = v[w].y;
            sRs[(k + 2) * 128 + ln] = v[w].z;
            sRs[(k + 3) * 128 + ln] = v[w].w;
            ssq += v[w].x * v[w].x + v[w].y * v[w].y
                 + v[w].z * v[w].z + v[w].w * v[w].w;
        }
        #pragma unroll
        for (int q = 0; q < 3; q++)
            sAs[tid + q * 256] = make_float2(a[q], a[q]);

        __syncthreads();   // tile staged

        #pragma unroll
        for (int k = 0; k < 32; k++) {
            ulonglong2 rv = *(const ulonglong2*)&sRs[k * 128 + prow];
            unsigned long long b0 = *(const unsigned long long*)&sAs[k * 24 + cbase + 0];
            unsigned long long b1 = *(const unsigned long long*)&sAs[k * 24 + cbase + 1];
            unsigned long long b2 = *(const unsigned long long*)&sAs[k * 24 + cbase + 2];
            fma2(acc[0][0], rv.x, b0); fma2(acc[0][1], rv.y, b0);
            fma2(acc[1][0], rv.x, b1); fma2(acc[1][1], rv.y, b1);
            fma2(acc[2][0], rv.x, b2); fma2(acc[2][1], rv.y, b2);
        }
    }

    // ---- write partial dots: g_part[kb][c][p]
    float* gp = g_part + (size_t)kb * 25 * PTOT;
    #pragma unroll
    for (int i = 0; i < 3; i++) {
        #pragma unroll
        for (int j = 0; j < 2; j++) {
            float2 f = unpk2(acc[i][j]);
            gp[(cbase + i) * PTOT + p0 + prow + j * 2 + 0] = f.x;
            gp[(cbase + i) * PTOT + p0 + prow + j * 2 + 1] = f.y;
        }
    }
    // ---- sumsq (c = 24): combine the two halves per n
    ssq += __shfl_xor_sync(0xffffffffu, ssq, 1);
    if (lh == 0)
        gp[24 * PTOT + p0 + ln] = ssq;
}

// ----------------------------------------------------------------------------
// Kernel 2: per-p alpha/sigmoid/Sinkhorn/beta -> 4x4 mixing matrix W.
// One thread per p. All 4x4 state in registers, fully unrolled.
// ----------------------------------------------------------------------------
__device__ __forceinline__ float sigm(float x) {
    return 1.0f / (1.0f + __expf(-x));
}

__global__ void sinkhorn_kernel(const float* __restrict__ sa,     // static_alpha [4][5]
                                const float* __restrict__ pbs,    // pre_branch_scale [1]
                                const float* __restrict__ rsc,    // residual_scale [1]
                                const float* __restrict__ sb,     // static_beta [4]
                                const float* __restrict__ hps) {  // h_post_scale [1]
    int p = blockIdx.x * 256 + threadIdx.x;
    if (p >= PTOT) return;

    float dots[25];
    #pragma unroll
    for (int c = 0; c < 25; c++) {
        float t = 0.0f;
        #pragma unroll
        for (int kb = 0; kb < KB_N; kb++)
            t += g_part[(size_t)kb * 25 * PTOT + c * PTOT + p];
        dots[c] = t;
    }

    // scale = sqrt(8192) / max(||x||, EPS); folds into every dot product
    const float scale = 90.50966799187809f / fmaxf(sqrtf(dots[24]), 1e-12f);
    const float ps = pbs[0] * scale;
    const float rs = rsc[0] * scale;

    float pre[4], M[4][4];
    #pragma unroll
    for (int si = 0; si < 4; si++) {
        pre[si] = sigm(dots[si * 5 + 0] * ps + sa[si * 5 + 0]);
        #pragma unroll
        for (int t = 0; t < 4; t++)
            M[si][t] = dots[si * 5 + t + 1] * rs + sa[si * 5 + t + 1];
    }

    // Sinkhorn: 20 x (column-LSE over s, then row-LSE over t)
    #pragma unroll
    for (int it = 0; it < 20; it++) {
        #pragma unroll
        for (int t = 0; t < 4; t++) {
            float m = fmaxf(fmaxf(M[0][t], M[1][t]), fmaxf(M[2][t], M[3][t]));
            float sum = __expf(M[0][t] - m) + __expf(M[1][t] - m)
                      + __expf(M[2][t] - m) + __expf(M[3][t] - m);
            float l = m + __logf(sum);
            M[0][t] -= l; M[1][t] -= l; M[2][t] -= l; M[3][t] -= l;
        }
        #pragma unroll
        for (int si = 0; si < 4; si++) {
            float m = fmaxf(fmaxf(M[si][0], M[si][1]), fmaxf(M[si][2], M[si][3]));
            float sum = __expf(M[si][0] - m) + __expf(M[si][1] - m)
                      + __expf(M[si][2] - m) + __expf(M[si][3] - m);
            float l = m + __logf(sum);
            M[si][0] -= l; M[si][1] -= l; M[si][2] -= l; M[si][3] -= l;
        }
    }

    const float hp = hps[0] * scale;
    #pragma unroll
    for (int q = 0; q < 4; q++) {
        float bq = 2.0f * sigm(dots[20 + q] * hp + sb[q]);
        #pragma unroll
        for (int si = 0; si < 4; si++)
            g_W[(size_t)p * 16 + q * 4 + si] = bq * pre[si] + __expf(M[si][q]);
    }
}

// ----------------------------------------------------------------------------
// Kernel 3: streaming mix. out[b*4+q, n, :] = sum_s W[q][s] * r[s, :]
// One CTA per (b,n). Pure HBM-bound: 32 KB in, 32 KB out per CTA.
// ----------------------------------------------------------------------------
__global__ __launch_bounds__(256) void mix_kernel(const float* __restrict__ res,
                                                  float* __restrict__ out) {
    const int bn = blockIdx.x;            // p = b*2048 + n
    const int b = bn >> 11, n = bn & 2047;

    __shared__ float sW[16];
    if (threadIdx.x < 16) sW[threadIdx.x] = g_W[(size_t)bn * 16 + threadIdx.x];
    __syncthreads();
    float w[16];
    #pragma unroll
    for (int i = 0; i < 16; i++) w[i] = sW[i];

    const size_t SSTR = (size_t)NVN * DV;  // stride between s-planes
    const float* rb = res + ((size_t)(b * 4) * NVN + n) * DV;
    float* ob       = out + ((size_t)(b * 4) * NVN + n) * DV;

    #pragma unroll
    for (int rep = 0; rep < 2; rep++) {
        int j = threadIdx.x * 4 + rep * 1024;
        float4 r0 = *(const float4*)(rb + 0 * SSTR + j);
        float4 r1 = *(const float4*)(rb + 1 * SSTR + j);
        float4 r2 = *(const float4*)(rb + 2 * SSTR + j);
        float4 r3 = *(const float4*)(rb + 3 * SSTR + j);
        #pragma unroll
        for (int q = 0; q < 4; q++) {
            const float w0 = w[q * 4 + 0], w1 = w[q * 4 + 1];
            const float w2 = w[q * 4 + 2], w3 = w[q * 4 + 3];
            float4 o;
            o.x = fmaf(w0, r0.x, fmaf(w1, r1.x, fmaf(w2, r2.x, w3 * r3.x)));
            o.y = fmaf(w0, r0.y, fmaf(w1, r1.y, fmaf(w2, r2.y, w3 * r3.y)));
            o.z = fmaf(w0, r0.z, fmaf(w1, r1.z, fmaf(w2, r2.z, w3 * r3.z)));
            o.w = fmaf(w0, r0.w, fmaf(w1, r1.w, fmaf(w2, r2.w, w3 * r3.w)));
            *(float4*)(ob + q * SSTR + j) = o;
        }
    }
}

// ----------------------------------------------------------------------------
// Launch
// ----------------------------------------------------------------------------
extern "C" void kernel_launch(void* const* d_in, const int* in_sizes, int n_in,
                              void* d_out, int out_size) {
    const float* residuals = (const float*)d_in[0];
    const float* gamma     = (const float*)d_in[1];
    const float* afn       = (const float*)d_in[2];
    const float* sa        = (const float*)d_in[3];
    const float* pbs       = (const float*)d_in[4];
    const float* rsc       = (const float*)d_in[5];
    const float* bfn       = (const float*)d_in[6];
    const float* sb        = (const float*)d_in[7];
    const float* hps       = (const float*)d_in[8];
    float* out = (float*)d_out;

    prep_kernel<<<(KTOT * NCOL + 255) / 256, 256>>>(afn, bfn, gamma);
    dots_kernel<<<dim3(64, 8), 256>>>(residuals);
    sinkhorn_kernel<<<PTOT / 256, 256>>>(sa, pbs, rsc, sb, hps);
    mix_kernel<<<PTOT, 256>>>(residuals, out);
}

// round 4
// speedup vs baseline: 1.1239x; 1.1239x over previous
#include <cuda_runtime.h>
#include <cstddef>

// Problem constants (fixed by the reference setup)
#define SV     4        // S
#define DV     2048     // DIM
#define NVN    2048     // N
#define BVB    4        // B
#define KTOT   8192     // S*DIM (reduction length)
#define NCOL   24       // 20 alpha cols + 4 beta cols
#define PTOT   8192     // B*N
#define KB_N   16       // K-split blocks (each 512)

// ----------------------------------------------------------------------------
// Scratch (static device globals; no runtime allocation allowed)
// ----------------------------------------------------------------------------
__device__ float2 g_Acomb2[KTOT * NCOL];        // duplicated-pair (1+gamma)*[afn|bfn]
__device__ float  g_part[KB_N * 25 * PTOT];     // partial dots: [kb][c][p], c=24 is sumsq
__device__ float  g_W[PTOT * 16];               // final 4x4 mixing matrix per (b,n)

// ----------------------------------------------------------------------------
// f32x2 packed-FMA helpers (Blackwell sm_100a+)
// ----------------------------------------------------------------------------
__device__ __forceinline__ void fma2(unsigned long long &d,
                                     unsigned long long a,
                                     unsigned long long b) {
    asm("fma.rn.f32x2 %0, %1, %2, %0;" : "+l"(d) : "l"(a), "l"(b));
}
__device__ __forceinline__ float2 unpk2(unsigned long long v) {
    float2 f;
    asm("mov.b64 {%0, %1}, %2;" : "=f"(f.x), "=f"(f.y) : "l"(v));
    return f;
}

// ----------------------------------------------------------------------------
// Kernel 0: build Acomb2 = duplicated pairs of (1+gamma) * [alpha_fn | beta_fn]
// ----------------------------------------------------------------------------
__global__ void prep_kernel(const float* __restrict__ afn,
                            const float* __restrict__ bfn,
                            const float* __restrict__ gamma) {
    int idx = blockIdx.x * 256 + threadIdx.x;
    if (idx >= KTOT * NCOL) return;
    int i = idx / NCOL;
    int c = idx - i * NCOL;
    float g = 1.0f + gamma[i];
    float v = (c < 20) ? afn[i * 20 + c] : bfn[i * 4 + (c - 20)];
    g_Acomb2[idx] = make_float2(v * g, v * g);
}

// ----------------------------------------------------------------------------
// Kernel 1: tall-skinny GEMM + sumsq, FMA-pipe-bound layout.
// Grid: (32 p-tiles of 256, 16 K-blocks of 512). 64 threads (2 warps).
// Thread tile: 4 p-rows x all 24 cols -> 48 fma2 per k per thread.
// Double-buffered smem, one barrier per 16-k stage.
// ----------------------------------------------------------------------------
__global__ __launch_bounds__(64) void dots_kernel(const float* __restrict__ res) {
    const int tid  = threadIdx.x;
    const int pt   = blockIdx.x;            // 0..31
    const int kb   = blockIdx.y;            // 0..15
    const int p0   = pt * 256;
    const int b    = p0 >> 11;
    const int n0   = p0 & 2047;
    const int kg   = kb * 512;              // global k start
    const int s    = kg >> 11;              // source s-plane
    const int kpl  = kg & 2047;             // k offset within plane

    __shared__ float  sR[2][16 * 256];      // [buf][k][p]  32 KB
    __shared__ float2 sA[2][16 * 24];       // [buf][k][c]  6 KB (dup pairs)

    const float* rbase = res + ((size_t)((b * 4 + s) * 2048 + n0)) * 2048 + kpl;

    const int lane = tid & 31, warp = tid >> 5;
    const int prow = warp * 128 + lane * 4;

    unsigned long long acc[24][2];
    #pragma unroll
    for (int c = 0; c < 24; c++) { acc[c][0] = 0ull; acc[c][1] = 0ull; }
    unsigned long long ssqa0 = 0ull, ssqa1 = 0ull;

    float4 v[16], av[3];

    // ---- stage loaders (16 k x 256 p residual block + 16x24 A block)
    #define LOAD_STAGE(st)                                                     \
        {                                                                      \
            _Pragma("unroll")                                                  \
            for (int a = 0; a < 16; a++) {                                     \
                int cch = tid + 64 * a;                                        \
                int row = cch >> 2;                                            \
                int jj  = (cch & 3) * 4;                                       \
                v[a] = *(const float4*)(rbase + (size_t)row * 2048             \
                                        + (st) * 16 + jj);                     \
            }                                                                  \
            const float4* ab = (const float4*)g_Acomb2                         \
                               + (size_t)(kg + (st) * 16) * 12;                \
            _Pragma("unroll")                                                  \
            for (int q = 0; q < 3; q++) av[q] = ab[tid + 64 * q];              \
        }

    #define STORE_STAGE(bf)                                                    \
        {                                                                      \
            _Pragma("unroll")                                                  \
            for (int a = 0; a < 16; a++) {                                     \
                int cch = tid + 64 * a;                                        \
                int row = cch >> 2;                                            \
                int k   = (cch & 3) * 4;                                       \
                sR[bf][(k + 0) * 256 + row] = v[a].x;                          \
                sR[bf][(k + 1) * 256 + row] = v[a].y;                          \
                sR[bf][(k + 2) * 256 + row] = v[a].z;                          \
                sR[bf][(k + 3) * 256 + row] = v[a].w;                          \
            }                                                                  \
            float4* sa4 = (float4*)&sA[bf][0];                                 \
            _Pragma("unroll")                                                  \
            for (int q = 0; q < 3; q++) sa4[tid + 64 * q] = av[q];             \
        }

    LOAD_STAGE(0);
    STORE_STAGE(0);
    __syncthreads();

    for (int st = 0; st < 32; st++) {
        const int buf = st & 1;
        if (st < 31) LOAD_STAGE(st + 1);

        #pragma unroll
        for (int k = 0; k < 16; k++) {
            ulonglong2 rv = *(const ulonglong2*)&sR[buf][k * 256 + prow];
            fma2(ssqa0, rv.x, rv.x);
            fma2(ssqa1, rv.y, rv.y);
            #pragma unroll
            for (int cc = 0; cc < 12; cc++) {
                ulonglong2 bb = *(const ulonglong2*)&sA[buf][k * 24 + cc * 2];
                fma2(acc[cc * 2 + 0][0], rv.x, bb.x);
                fma2(acc[cc * 2 + 0][1], rv.y, bb.x);
                fma2(acc[cc * 2 + 1][0], rv.x, bb.y);
                fma2(acc[cc * 2 + 1][1], rv.y, bb.y);
            }
        }

        if (st < 31) STORE_STAGE(buf ^ 1);
        __syncthreads();
    }
    #undef LOAD_STAGE
    #undef STORE_STAGE

    // ---- write partial dots: g_part[kb][c][p], coalesced float4 per col
    float* gp = g_part + (size_t)kb * (25 * PTOT);
    #pragma unroll
    for (int c = 0; c < 24; c++) {
        float2 lo = unpk2(acc[c][0]);
        float2 hi = unpk2(acc[c][1]);
        float4 o = make_float4(lo.x, lo.y, hi.x, hi.y);
        *(float4*)(gp + (size_t)c * PTOT + p0 + prow) = o;
    }
    {
        float2 s0 = unpk2(ssqa0);
        float2 s1 = unpk2(ssqa1);
        float4 o = make_float4(s0.x, s0.y, s1.x, s1.y);
        *(float4*)(gp + (size_t)24 * PTOT + p0 + prow) = o;
    }
}

// ----------------------------------------------------------------------------
// Kernel 2: per-p alpha/sigmoid/Sinkhorn/beta -> 4x4 mixing matrix W.
// ----------------------------------------------------------------------------
__device__ __forceinline__ float sigm(float x) {
    return 1.0f / (1.0f + __expf(-x));
}

__global__ void sinkhorn_kernel(const float* __restrict__ sa,     // static_alpha [4][5]
                                const float* __restrict__ pbs,    // pre_branch_scale [1]
                                const float* __restrict__ rsc,    // residual_scale [1]
                                const float* __restrict__ sb,     // static_beta [4]
                                const float* __restrict__ hps) {  // h_post_scale [1]
    int p = blockIdx.x * 256 + threadIdx.x;
    if (p >= PTOT) return;

    float dots[25];
    #pragma unroll
    for (int c = 0; c < 25; c++) {
        float t = 0.0f;
        #pragma unroll
        for (int kb = 0; kb < KB_N; kb++)
            t += g_part[(size_t)kb * 25 * PTOT + c * PTOT + p];
        dots[c] = t;
    }

    // scale = sqrt(8192) / max(||x||, EPS); folds into every dot product
    const float scale = 90.50966799187809f / fmaxf(sqrtf(dots[24]), 1e-12f);
    const float ps = pbs[0] * scale;
    const float rs = rsc[0] * scale;

    float pre[4], M[4][4];
    #pragma unroll
    for (int si = 0; si < 4; si++) {
        pre[si] = sigm(dots[si * 5 + 0] * ps + sa[si * 5 + 0]);
        #pragma unroll
        for (int t = 0; t < 4; t++)
            M[si][t] = dots[si * 5 + t + 1] * rs + sa[si * 5 + t + 1];
    }

    // Sinkhorn: 20 x (column-LSE over s, then row-LSE over t)
    #pragma unroll
    for (int it = 0; it < 20; it++) {
        #pragma unroll
        for (int t = 0; t < 4; t++) {
            float m = fmaxf(fmaxf(M[0][t], M[1][t]), fmaxf(M[2][t], M[3][t]));
            float sum = __expf(M[0][t] - m) + __expf(M[1][t] - m)
                      + __expf(M[2][t] - m) + __expf(M[3][t] - m);
            float l = m + __logf(sum);
            M[0][t] -= l; M[1][t] -= l; M[2][t] -= l; M[3][t] -= l;
        }
        #pragma unroll
        for (int si = 0; si < 4; si++) {
            float m = fmaxf(fmaxf(M[si][0], M[si][1]), fmaxf(M[si][2], M[si][3]));
            float sum = __expf(M[si][0] - m) + __expf(M[si][1] - m)
                      + __expf(M[si][2] - m) + __expf(M[si][3] - m);
            float l = m + __logf(sum);
            M[si][0] -= l; M[si][1] -= l; M[si][2] -= l; M[si][3] -= l;
        }
    }

    const float hp = hps[0] * scale;
    #pragma unroll
    for (int q = 0; q < 4; q++) {
        float bq = 2.0f * sigm(dots[20 + q] * hp + sb[q]);
        #pragma unroll
        for (int si = 0; si < 4; si++)
            g_W[(size_t)p * 16 + q * 4 + si] = bq * pre[si] + __expf(M[si][q]);
    }
}

// ----------------------------------------------------------------------------
// Kernel 3: streaming mix. out[b*4+q, n, :] = sum_s W[q][s] * r[s, :]
// One CTA per (b,n). Pure HBM-bound: proven 6.3 TB/s — unchanged.
// ----------------------------------------------------------------------------
__global__ __launch_bounds__(256) void mix_kernel(const float* __restrict__ res,
                                                  float* __restrict__ out) {
    const int bn = blockIdx.x;            // p = b*2048 + n
    const int b = bn >> 11, n = bn & 2047;

    __shared__ float sW[16];
    if (threadIdx.x < 16) sW[threadIdx.x] = g_W[(size_t)bn * 16 + threadIdx.x];
    __syncthreads();
    float w[16];
    #pragma unroll
    for (int i = 0; i < 16; i++) w[i] = sW[i];

    const size_t SSTR = (size_t)NVN * DV;  // stride between s-planes
    const float* rb = res + ((size_t)(b * 4) * NVN + n) * DV;
    float* ob       = out + ((size_t)(b * 4) * NVN + n) * DV;

    #pragma unroll
    for (int rep = 0; rep < 2; rep++) {
        int j = threadIdx.x * 4 + rep * 1024;
        float4 r0 = *(const float4*)(rb + 0 * SSTR + j);
        float4 r1 = *(const float4*)(rb + 1 * SSTR + j);
        float4 r2 = *(const float4*)(rb + 2 * SSTR + j);
        float4 r3 = *(const float4*)(rb + 3 * SSTR + j);
        #pragma unroll
        for (int q = 0; q < 4; q++) {
            const float w0 = w[q * 4 + 0], w1 = w[q * 4 + 1];
            const float w2 = w[q * 4 + 2], w3 = w[q * 4 + 3];
            float4 o;
            o.x = fmaf(w0, r0.x, fmaf(w1, r1.x, fmaf(w2, r2.x, w3 * r3.x)));
            o.y = fmaf(w0, r0.y, fmaf(w1, r1.y, fmaf(w2, r2.y, w3 * r3.y)));
            o.z = fmaf(w0, r0.z, fmaf(w1, r1.z, fmaf(w2, r2.z, w3 * r3.z)));
            o.w = fmaf(w0, r0.w, fmaf(w1, r1.w, fmaf(w2, r2.w, w3 * r3.w)));
            *(float4*)(ob + q * SSTR + j) = o;
        }
    }
}

// ----------------------------------------------------------------------------
// Launch
// ----------------------------------------------------------------------------
extern "C" void kernel_launch(void* const* d_in, const int* in_sizes, int n_in,
                              void* d_out, int out_size) {
    const float* residuals = (const float*)d_in[0];
    const float* gamma     = (const float*)d_in[1];
    const float* afn       = (const float*)d_in[2];
    const float* sa        = (const float*)d_in[3];
    const float* pbs       = (const float*)d_in[4];
    const float* rsc       = (const float*)d_in[5];
    const float* bfn       = (const float*)d_in[6];
    const float* sb        = (const float*)d_in[7];
    const float* hps       = (const float*)d_in[8];
    float* out = (float*)d_out;

    prep_kernel<<<(KTOT * NCOL + 255) / 256, 256>>>(afn, bfn, gamma);
    dots_kernel<<<dim3(32, 16), 64>>>(residuals);
    sinkhorn_kernel<<<PTOT / 256, 256>>>(sa, pbs, rsc, sb, hps);
    mix_kernel<<<PTOT, 256>>>(residuals, out);
}